// round 1
// baseline (speedup 1.0000x reference)
#include <cuda_runtime.h>

#define Nn 100000
#define Ee 1600000
#define Dd 128
#define Hh 256
#define Ll 40

// ---------------- scratch (module-load allocated, not runtime alloc) ----------
__device__ float g_deg[Nn];
__device__ float g_dinv[Nn];
__device__ float g_bufA[(size_t)Nn * Dd];   // aggregation accumulator
__device__ float g_bufB[(size_t)Nn * Dd];   // layer activations
__device__ float g_hid[(size_t)Nn * Hh];    // MLP hidden

// ---------------- degree / normalization --------------------------------------
__global__ void k_deg_init(float* __restrict__ deg, int n) {
    int i = blockIdx.x * blockDim.x + threadIdx.x;
    if (i < n) deg[i] = 1.0f;   // self-loop contributes 1
}

__global__ void k_deg_acc(const int* __restrict__ row, float* __restrict__ deg, int e) {
    int i = blockIdx.x * blockDim.x + threadIdx.x;
    if (i < e) atomicAdd(&deg[row[i]], 1.0f);
}

__global__ void k_dinv(const float* __restrict__ deg, float* __restrict__ dinv, int n) {
    int i = blockIdx.x * blockDim.x + threadIdx.x;
    if (i < n) dinv[i] = rsqrtf(deg[i]);   // deg >= 1 always (self loops)
}

// ---------------- self-loop init: agg[i] = src[i] * dinv[i]^2 ------------------
__global__ void k_selfinit(const float4* __restrict__ src, const float* __restrict__ dinv,
                           float4* __restrict__ dst, int n) {
    int t = blockIdx.x * blockDim.x + threadIdx.x;
    if (t < n * (Dd / 4)) {
        int node = t >> 5;              // Dd/4 == 32 chunks per node
        float w = dinv[node]; w *= w;
        float4 v = src[t];
        v.x *= w; v.y *= w; v.z *= w; v.w *= w;
        dst[t] = v;
    }
}

// ---------------- edge scatter: one warp per edge, vector RED ------------------
__global__ void k_scatter(const int* __restrict__ ei, const float* __restrict__ dinv,
                          const float4* __restrict__ src, float4* __restrict__ dst, int e) {
    int gw   = (int)((blockIdx.x * (size_t)blockDim.x + threadIdx.x) >> 5);
    int lane = threadIdx.x & 31;
    if (gw >= e) return;
    int r = __ldg(&ei[gw]);        // edge_index[0][e]  (destination / segment id)
    int c = __ldg(&ei[e + gw]);    // edge_index[1][e]  (source)
    float w = dinv[r] * dinv[c];
    float4 v = src[(size_t)c * 32 + lane];
    float4* p = dst + (size_t)r * 32 + lane;
    asm volatile("red.global.add.v4.f32 [%0], {%1, %2, %3, %4};"
                 :: "l"(p), "f"(v.x * w), "f"(v.y * w), "f"(v.z * w), "f"(v.w * w)
                 : "memory");
}

// ---------------- fp32 GEMM: out = (relu?)(A @ W + b), W resident in smem ------
// 256 threads; thread grid TX x TY, each thread computes TM x TN outputs.
template<int K, int NO, int TM, int TN, bool RELU>
__global__ void k_gemm(const float* __restrict__ A, const float* __restrict__ W,
                       const float* __restrict__ bias, float* __restrict__ out, int n) {
    constexpr int TX     = NO / TN;
    constexpr int TY     = 256 / TX;
    constexpr int TILE_M = TY * TM;
    constexpr int KP     = K + 1;          // pad to break A bank conflicts
    extern __shared__ float sm[];
    float* Ws = sm;                        // K * NO
    float* As = sm + K * NO;               // TILE_M * KP

    int tid = threadIdx.x;

    // cooperative W load (float4)
    {
        const float4* W4  = (const float4*)W;
        float4*       Ws4 = (float4*)Ws;
        for (int i = tid; i < K * NO / 4; i += 256) Ws4[i] = W4[i];
    }
    // cooperative A-tile load (float4, zero-padded past n)
    int m0 = blockIdx.x * TILE_M;
    for (int i = tid; i < TILE_M * K / 4; i += 256) {
        int r = (i * 4) / K, k = (i * 4) % K;
        int gr = m0 + r;
        float4 v = (gr < n) ? ((const float4*)A)[(size_t)gr * (K / 4) + (k / 4)]
                            : make_float4(0.f, 0.f, 0.f, 0.f);
        As[r * KP + k]     = v.x;
        As[r * KP + k + 1] = v.y;
        As[r * KP + k + 2] = v.z;
        As[r * KP + k + 3] = v.w;
    }
    __syncthreads();

    int tx = tid % TX, ty = tid / TX;

    float acc[TM][TN];
#pragma unroll
    for (int i = 0; i < TM; i++)
#pragma unroll
        for (int j = 0; j < TN; j++) acc[i][j] = 0.f;

#pragma unroll 8
    for (int k = 0; k < K; k++) {
        float a[TM];
#pragma unroll
        for (int i = 0; i < TM; i++) a[i] = As[(ty * TM + i) * KP + k];
        float w[TN];
        if constexpr (TN == 8) {
            float4 w0 = *(const float4*)&Ws[k * NO + tx * TN];
            float4 w1 = *(const float4*)&Ws[k * NO + tx * TN + 4];
            w[0] = w0.x; w[1] = w0.y; w[2] = w0.z; w[3] = w0.w;
            w[4] = w1.x; w[5] = w1.y; w[6] = w1.z; w[7] = w1.w;
        } else {
#pragma unroll
            for (int j = 0; j < TN; j++) w[j] = Ws[k * NO + tx * TN + j];
        }
#pragma unroll
        for (int i = 0; i < TM; i++)
#pragma unroll
            for (int j = 0; j < TN; j++)
                acc[i][j] = fmaf(a[i], w[j], acc[i][j]);
    }

    // epilogue: bias (+ relu) + store
    float bv[TN];
#pragma unroll
    for (int j = 0; j < TN; j++) bv[j] = bias[tx * TN + j];

#pragma unroll
    for (int i = 0; i < TM; i++) {
        int gr = m0 + ty * TM + i;
        if (gr < n) {
#pragma unroll
            for (int j = 0; j < TN; j++) {
                float v = acc[i][j] + bv[j];
                if (RELU) v = fmaxf(v, 0.f);
                out[(size_t)gr * NO + tx * TN + j] = v;
            }
        }
    }
}

// smem byte sizes per instantiation
#define SMEM_LAYER ((128 * 128 + 64 * 129) * 4)   // 98560
#define SMEM_MLP1  ((128 * 256 + 64 * 129) * 4)   // 164096
#define SMEM_MLP2  ((256 * 40 + 64 * 257) * 4)    // 106752

extern "C" void kernel_launch(void* const* d_in, const int* in_sizes, int n_in,
                              void* d_out, int out_size) {
    const float* x   = (const float*)d_in[0];
    const int*   ei  = (const int*)  d_in[1];
    const float* W0  = (const float*)d_in[2];
    const float* b0  = (const float*)d_in[3];
    const float* W1  = (const float*)d_in[4];
    const float* b1  = (const float*)d_in[5];
    const float* W2  = (const float*)d_in[6];
    const float* b2  = (const float*)d_in[7];
    const float* Wm1 = (const float*)d_in[8];
    const float* bm1 = (const float*)d_in[9];
    const float* Wm2 = (const float*)d_in[10];
    const float* bm2 = (const float*)d_in[11];
    float* out = (float*)d_out;

    const int n = Nn;
    const int e = Ee;

    float *deg, *dinv, *bufA, *bufB, *hid;
    cudaGetSymbolAddress((void**)&deg,  g_deg);
    cudaGetSymbolAddress((void**)&dinv, g_dinv);
    cudaGetSymbolAddress((void**)&bufA, g_bufA);
    cudaGetSymbolAddress((void**)&bufB, g_bufB);
    cudaGetSymbolAddress((void**)&hid,  g_hid);

    cudaFuncSetAttribute(k_gemm<128, 128, 4, 8, true>,
                         cudaFuncAttributeMaxDynamicSharedMemorySize, SMEM_LAYER);
    cudaFuncSetAttribute(k_gemm<128, 256, 8, 8, true>,
                         cudaFuncAttributeMaxDynamicSharedMemorySize, SMEM_MLP1);
    cudaFuncSetAttribute(k_gemm<256, 40, 1, 10, false>,
                         cudaFuncAttributeMaxDynamicSharedMemorySize, SMEM_MLP2);

    const int TB = 256;
    dim3 gN((n + TB - 1) / TB);
    dim3 gE((e + TB - 1) / TB);
    dim3 gND4(((size_t)n * 32 + TB - 1) / TB);          // n * Dd/4 threads
    dim3 gEW(((size_t)e * 32 + TB - 1) / TB);           // e warps
    dim3 gGemm((n + 63) / 64);

    // ---- normalization ----
    k_deg_init<<<gN, TB>>>(deg, n);
    k_deg_acc <<<gE, TB>>>(ei, deg, e);
    k_dinv    <<<gN, TB>>>(deg, dinv, n);

    // ---- layer 0: x -> bufA(agg) -> bufB(h1) ----
    k_selfinit<<<gND4, TB>>>((const float4*)x, dinv, (float4*)bufA, n);
    k_scatter <<<gEW, TB>>>(ei, dinv, (const float4*)x, (float4*)bufA, e);
    k_gemm<128, 128, 4, 8, true><<<gGemm, TB, SMEM_LAYER>>>(bufA, W0, b0, bufB, n);

    // ---- layer 1: bufB -> bufA(agg) -> bufB(h2) ----
    k_selfinit<<<gND4, TB>>>((const float4*)bufB, dinv, (float4*)bufA, n);
    k_scatter <<<gEW, TB>>>(ei, dinv, (const float4*)bufB, (float4*)bufA, e);
    k_gemm<128, 128, 4, 8, true><<<gGemm, TB, SMEM_LAYER>>>(bufA, W1, b1, bufB, n);

    // ---- layer 2: bufB -> bufA(agg) -> bufB(h3) ----
    k_selfinit<<<gND4, TB>>>((const float4*)bufB, dinv, (float4*)bufA, n);
    k_scatter <<<gEW, TB>>>(ei, dinv, (const float4*)bufB, (float4*)bufA, e);
    k_gemm<128, 128, 4, 8, true><<<gGemm, TB, SMEM_LAYER>>>(bufA, W2, b2, bufB, n);

    // ---- MLP: h3 @ Wm1 -> relu -> @ Wm2 + bm2 ----
    k_gemm<128, 256, 8, 8, true ><<<gGemm, TB, SMEM_MLP1>>>(bufB, Wm1, bm1, hid, n);
    k_gemm<256, 40, 1, 10, false><<<gGemm, TB, SMEM_MLP2>>>(hid, Wm2, bm2, out, n);
}

// round 2
// speedup vs baseline: 1.2692x; 1.2692x over previous
#include <cuda_runtime.h>

#define Nn 100000
#define Ee 1600000
#define Dd 128
#define Hh 256
#define Ll 40

// ---------------- scratch (module-load allocated, not runtime alloc) ----------
__device__ int   g_degi[Nn];                // int degree / fill cursor
__device__ int   g_offs[Nn + 1];            // CSR row offsets
__device__ int   g_col[Ee];                 // CSR column (source node) per edge
__device__ float g_dinv[Nn];
__device__ float g_bufA[(size_t)Nn * Dd];   // aggregation result
__device__ float g_bufB[(size_t)Nn * Dd];   // layer activations
__device__ float g_hid[(size_t)Nn * Hh];    // MLP hidden

// ---------------- CSR build ----------------------------------------------------
__global__ void k_zero(int* __restrict__ a, int n) {
    int i = blockIdx.x * blockDim.x + threadIdx.x;
    if (i < n) a[i] = 0;
}

__global__ void k_count(const int* __restrict__ ei, int* __restrict__ degi, int e) {
    int i = blockIdx.x * blockDim.x + threadIdx.x;
    if (i < e) atomicAdd(&degi[ei[i]], 1);   // row = ei[0][i]
}

__global__ void k_dinv(const int* __restrict__ degi, float* __restrict__ dinv, int n) {
    int i = blockIdx.x * blockDim.x + threadIdx.x;
    if (i < n) dinv[i] = rsqrtf((float)degi[i] + 1.0f);   // +1 self loop
}

// single-block exclusive scan of degi -> offs (Nn elements + total)
__global__ void k_scan(const int* __restrict__ degi, int* __restrict__ offs) {
    __shared__ int ssum[1024];
    int t = threadIdx.x;
    const int CH = (Nn + 1023) / 1024;
    int beg = t * CH, end = min(beg + CH, Nn);
    int s = 0;
    for (int i = beg; i < end; i++) s += degi[i];
    ssum[t] = s;
    __syncthreads();
    for (int d = 1; d < 1024; d <<= 1) {
        int v = (t >= d) ? ssum[t - d] : 0;
        __syncthreads();
        ssum[t] += v;
        __syncthreads();
    }
    int run = (t == 0) ? 0 : ssum[t - 1];
    for (int i = beg; i < end; i++) { offs[i] = run; run += degi[i]; }
    if (t == 1023) offs[Nn] = ssum[1023];
}

__global__ void k_fill(const int* __restrict__ ei, const int* __restrict__ offs,
                       int* __restrict__ cursor, int* __restrict__ col, int e) {
    int i = blockIdx.x * blockDim.x + threadIdx.x;
    if (i < e) {
        int r = ei[i];
        int c = ei[e + i];
        int pos = offs[r] + atomicAdd(&cursor[r], 1);
        col[pos] = c;
    }
}

// ---------------- aggregation: one warp per node, register accumulate ----------
// agg[r] = dinv[r] * ( dinv[r]*x[r] + sum_{c in N(r)} dinv[c]*x[c] )
__global__ void k_gather(const int* __restrict__ offs, const int* __restrict__ col,
                         const float* __restrict__ dinv, const float4* __restrict__ src,
                         float4* __restrict__ dst) {
    int w    = (int)((blockIdx.x * (size_t)blockDim.x + threadIdx.x) >> 5);
    int lane = threadIdx.x & 31;
    if (w >= Nn) return;

    float di = __ldg(&dinv[w]);
    float4 acc = __ldg(&src[(size_t)w * 32 + lane]);
    acc.x *= di; acc.y *= di; acc.z *= di; acc.w *= di;

    int beg = __ldg(&offs[w]), end = __ldg(&offs[w + 1]);
    int c = (beg < end) ? __ldg(&col[beg]) : 0;
    for (int j = beg; j < end; j++) {
        int cn = (j + 1 < end) ? __ldg(&col[j + 1]) : 0;   // prefetch next index
        float wc = __ldg(&dinv[c]);
        float4 v = __ldg(&src[(size_t)c * 32 + lane]);
        acc.x = fmaf(wc, v.x, acc.x);
        acc.y = fmaf(wc, v.y, acc.y);
        acc.z = fmaf(wc, v.z, acc.z);
        acc.w = fmaf(wc, v.w, acc.w);
        c = cn;
    }
    acc.x *= di; acc.y *= di; acc.z *= di; acc.w *= di;
    dst[(size_t)w * 32 + lane] = acc;
}

// ---------------- fp32 GEMM: out = (relu?)(A @ W + b), W resident in smem ------
template<int K, int NO, int TM, int TN, bool RELU>
__global__ void k_gemm(const float* __restrict__ A, const float* __restrict__ W,
                       const float* __restrict__ bias, float* __restrict__ out, int n) {
    constexpr int TX     = NO / TN;
    constexpr int TY     = 256 / TX;
    constexpr int TILE_M = TY * TM;
    constexpr int KP     = K + 1;
    extern __shared__ float sm[];
    float* Ws = sm;                        // K * NO
    float* As = sm + K * NO;               // TILE_M * KP

    int tid = threadIdx.x;

    {
        const float4* W4  = (const float4*)W;
        float4*       Ws4 = (float4*)Ws;
        for (int i = tid; i < K * NO / 4; i += 256) Ws4[i] = W4[i];
    }
    int m0 = blockIdx.x * TILE_M;
    for (int i = tid; i < TILE_M * K / 4; i += 256) {
        int r = (i * 4) / K, k = (i * 4) % K;
        int gr = m0 + r;
        float4 v = (gr < n) ? ((const float4*)A)[(size_t)gr * (K / 4) + (k / 4)]
                            : make_float4(0.f, 0.f, 0.f, 0.f);
        As[r * KP + k]     = v.x;
        As[r * KP + k + 1] = v.y;
        As[r * KP + k + 2] = v.z;
        As[r * KP + k + 3] = v.w;
    }
    __syncthreads();

    int tx = tid % TX, ty = tid / TX;

    float acc[TM][TN];
#pragma unroll
    for (int i = 0; i < TM; i++)
#pragma unroll
        for (int j = 0; j < TN; j++) acc[i][j] = 0.f;

#pragma unroll 8
    for (int k = 0; k < K; k++) {
        float a[TM];
#pragma unroll
        for (int i = 0; i < TM; i++) a[i] = As[(ty * TM + i) * KP + k];
        float w[TN];
        if constexpr (TN == 8) {
            float4 w0 = *(const float4*)&Ws[k * NO + tx * TN];
            float4 w1 = *(const float4*)&Ws[k * NO + tx * TN + 4];
            w[0] = w0.x; w[1] = w0.y; w[2] = w0.z; w[3] = w0.w;
            w[4] = w1.x; w[5] = w1.y; w[6] = w1.z; w[7] = w1.w;
        } else {
#pragma unroll
            for (int j = 0; j < TN; j++) w[j] = Ws[k * NO + tx * TN + j];
        }
#pragma unroll
        for (int i = 0; i < TM; i++)
#pragma unroll
            for (int j = 0; j < TN; j++)
                acc[i][j] = fmaf(a[i], w[j], acc[i][j]);
    }

    float bv[TN];
#pragma unroll
    for (int j = 0; j < TN; j++) bv[j] = bias[tx * TN + j];

#pragma unroll
    for (int i = 0; i < TM; i++) {
        int gr = m0 + ty * TM + i;
        if (gr < n) {
#pragma unroll
            for (int j = 0; j < TN; j++) {
                float v = acc[i][j] + bv[j];
                if (RELU) v = fmaxf(v, 0.f);
                out[(size_t)gr * NO + tx * TN + j] = v;
            }
        }
    }
}

// smem byte sizes per instantiation
#define SMEM_LAYER ((128 * 128 + 128 * 129) * 4)  // 131584  (TILE_M = 128)
#define SMEM_MLP1  ((128 * 256 + 64 * 129) * 4)   // 164096
#define SMEM_MLP2  ((256 * 40 + 64 * 257) * 4)    // 106752

extern "C" void kernel_launch(void* const* d_in, const int* in_sizes, int n_in,
                              void* d_out, int out_size) {
    const float* x   = (const float*)d_in[0];
    const int*   ei  = (const int*)  d_in[1];
    const float* W0  = (const float*)d_in[2];
    const float* b0  = (const float*)d_in[3];
    const float* W1  = (const float*)d_in[4];
    const float* b1  = (const float*)d_in[5];
    const float* W2  = (const float*)d_in[6];
    const float* b2  = (const float*)d_in[7];
    const float* Wm1 = (const float*)d_in[8];
    const float* bm1 = (const float*)d_in[9];
    const float* Wm2 = (const float*)d_in[10];
    const float* bm2 = (const float*)d_in[11];
    float* out = (float*)d_out;

    const int n = Nn;
    const int e = Ee;

    int *degi, *offs, *col;
    float *dinv, *bufA, *bufB, *hid;
    cudaGetSymbolAddress((void**)&degi, g_degi);
    cudaGetSymbolAddress((void**)&offs, g_offs);
    cudaGetSymbolAddress((void**)&col,  g_col);
    cudaGetSymbolAddress((void**)&dinv, g_dinv);
    cudaGetSymbolAddress((void**)&bufA, g_bufA);
    cudaGetSymbolAddress((void**)&bufB, g_bufB);
    cudaGetSymbolAddress((void**)&hid,  g_hid);

    cudaFuncSetAttribute(k_gemm<128, 128, 8, 8, true>,
                         cudaFuncAttributeMaxDynamicSharedMemorySize, SMEM_LAYER);
    cudaFuncSetAttribute(k_gemm<128, 256, 8, 8, true>,
                         cudaFuncAttributeMaxDynamicSharedMemorySize, SMEM_MLP1);
    cudaFuncSetAttribute(k_gemm<256, 40, 1, 10, false>,
                         cudaFuncAttributeMaxDynamicSharedMemorySize, SMEM_MLP2);

    const int TB = 256;
    dim3 gN((n + TB - 1) / TB);
    dim3 gE((e + TB - 1) / TB);
    dim3 gNW(((size_t)n * 32 + TB - 1) / TB);           // n warps (gather)
    dim3 gGemm128((n + 127) / 128);
    dim3 gGemm64((n + 63) / 64);

    // ---- CSR build + normalization ----
    k_zero <<<gN, TB>>>(degi, n);
    k_count<<<gE, TB>>>(ei, degi, e);
    k_dinv <<<gN, TB>>>(degi, dinv, n);
    k_scan <<<1, 1024>>>(degi, offs);
    k_zero <<<gN, TB>>>(degi, n);
    k_fill <<<gE, TB>>>(ei, offs, degi, col, e);

    // ---- layer 0 ----
    k_gather<<<gNW, TB>>>(offs, col, dinv, (const float4*)x, (float4*)bufA);
    k_gemm<128, 128, 8, 8, true><<<gGemm128, TB, SMEM_LAYER>>>(bufA, W0, b0, bufB, n);

    // ---- layer 1 ----
    k_gather<<<gNW, TB>>>(offs, col, dinv, (const float4*)bufB, (float4*)bufA);
    k_gemm<128, 128, 8, 8, true><<<gGemm128, TB, SMEM_LAYER>>>(bufA, W1, b1, bufB, n);

    // ---- layer 2 ----
    k_gather<<<gNW, TB>>>(offs, col, dinv, (const float4*)bufB, (float4*)bufA);
    k_gemm<128, 128, 8, 8, true><<<gGemm128, TB, SMEM_LAYER>>>(bufA, W2, b2, bufB, n);

    // ---- MLP ----
    k_gemm<128, 256, 8, 8, true ><<<gGemm64, TB, SMEM_MLP1>>>(bufB, Wm1, bm1, hid, n);
    k_gemm<256, 40, 1, 10, false><<<gGemm64, TB, SMEM_MLP2>>>(hid, Wm2, bm2, out, n);
}

// round 3
// speedup vs baseline: 2.5058x; 1.9743x over previous
#include <cuda_runtime.h>
#include <cuda_bf16.h>

#define Nn 100000
#define Ee 1600000
#define Dd 128
#define Hh 256
#define Ll 40
#define NB 98   // ceil(Nn / 1024)

// ---------------- scratch ------------------------------------------------------
__device__ int   g_degi[Nn];
__device__ int   g_offs[Nn + 1];
__device__ int   g_col[Ee];
__device__ int   g_part[NB];
__device__ int   g_base[NB];
__device__ float g_dinv[Nn];
__device__ float g_bufA[(size_t)Nn * Dd];
__device__ float g_bufB[(size_t)Nn * Dd];
__device__ float g_hid[(size_t)Nn * Hh];
// transposed bf16 hi/lo weights: W0,W1,W2 (128x128 each), Wm1 (256 rows x 128)
#define WT0 0
#define WT1 16384
#define WT2 32768
#define WTM1 49152
__device__ __nv_bfloat16 g_wtH[81920];
__device__ __nv_bfloat16 g_wtL[81920];

// ---------------- CSR build ----------------------------------------------------
__global__ void k_zero(int* __restrict__ a, int n) {
    int i = blockIdx.x * blockDim.x + threadIdx.x;
    if (i < n) a[i] = 0;
}

__global__ void k_count(const int* __restrict__ ei, int* __restrict__ degi, int e) {
    int i = blockIdx.x * blockDim.x + threadIdx.x;
    if (i < e) atomicAdd(&degi[ei[i]], 1);
}

__global__ void k_dinv(const int* __restrict__ degi, float* __restrict__ dinv, int n) {
    int i = blockIdx.x * blockDim.x + threadIdx.x;
    if (i < n) dinv[i] = rsqrtf((float)degi[i] + 1.0f);
}

// block partial sums
__global__ void k_scanA(const int* __restrict__ degi, int* __restrict__ part) {
    __shared__ int s[1024];
    int i = blockIdx.x * 1024 + threadIdx.x;
    s[threadIdx.x] = (i < Nn) ? degi[i] : 0;
    __syncthreads();
    for (int d = 512; d > 0; d >>= 1) {
        if (threadIdx.x < d) s[threadIdx.x] += s[threadIdx.x + d];
        __syncthreads();
    }
    if (threadIdx.x == 0) part[blockIdx.x] = s[0];
}

// exclusive scan of NB partials (single small block)
__global__ void k_scanB(const int* __restrict__ part, int* __restrict__ base) {
    __shared__ int s[128];
    int t = threadIdx.x;
    int v = (t < NB) ? part[t] : 0;
    s[t] = v;
    __syncthreads();
    for (int d = 1; d < 128; d <<= 1) {
        int u = (t >= d) ? s[t - d] : 0;
        __syncthreads();
        s[t] += u;
        __syncthreads();
    }
    if (t < NB) base[t] = s[t] - v;   // exclusive
}

// per-block exclusive scan + base -> offs
__global__ void k_scanC(const int* __restrict__ degi, const int* __restrict__ base,
                        int* __restrict__ offs) {
    __shared__ int s[1024];
    int t = threadIdx.x;
    int i = blockIdx.x * 1024 + t;
    int v = (i < Nn) ? degi[i] : 0;
    s[t] = v;
    __syncthreads();
    for (int d = 1; d < 1024; d <<= 1) {
        int u = (t >= d) ? s[t - d] : 0;
        __syncthreads();
        s[t] += u;
        __syncthreads();
    }
    int exc = s[t] - v + base[blockIdx.x];
    if (i < Nn) {
        offs[i] = exc;
        if (i == Nn - 1) offs[Nn] = exc + v;
    }
}

// fill CSR; consumes degi as a countdown cursor
__global__ void k_fill(const int* __restrict__ ei, const int* __restrict__ offs,
                       int* __restrict__ degi, int* __restrict__ col, int e) {
    int i = blockIdx.x * blockDim.x + threadIdx.x;
    if (i < e) {
        int r = ei[i];
        int c = ei[e + i];
        int pos = offs[r] + atomicSub(&degi[r], 1) - 1;
        col[pos] = c;
    }
}

// ---------------- weight conversion: W[K][N] -> Wt hi/lo [N][K] bf16 -----------
__global__ void k_wconv(const float* __restrict__ W, __nv_bfloat16* __restrict__ H,
                        __nv_bfloat16* __restrict__ L, int K, int N) {
    int i = blockIdx.x * blockDim.x + threadIdx.x;
    if (i < K * N) {
        int k = i / N, n = i % N;
        float w = W[i];
        __nv_bfloat16 h = __float2bfloat16(w);
        __nv_bfloat16 l = __float2bfloat16(w - __bfloat162float(h));
        H[(size_t)n * K + k] = h;
        L[(size_t)n * K + k] = l;
    }
}

// ---------------- aggregation: one warp per node -------------------------------
__global__ void k_gather(const int* __restrict__ offs, const int* __restrict__ col,
                         const float* __restrict__ dinv, const float4* __restrict__ src,
                         float4* __restrict__ dst) {
    int w    = (int)((blockIdx.x * (size_t)blockDim.x + threadIdx.x) >> 5);
    int lane = threadIdx.x & 31;
    if (w >= Nn) return;

    float di = __ldg(&dinv[w]);
    float4 acc = __ldg(&src[(size_t)w * 32 + lane]);
    acc.x *= di; acc.y *= di; acc.z *= di; acc.w *= di;

    int beg = __ldg(&offs[w]), end = __ldg(&offs[w + 1]);
    int c = (beg < end) ? __ldg(&col[beg]) : 0;
    for (int j = beg; j < end; j++) {
        int cn = (j + 1 < end) ? __ldg(&col[j + 1]) : 0;
        float wc = __ldg(&dinv[c]);
        float4 v = __ldg(&src[(size_t)c * 32 + lane]);
        acc.x = fmaf(wc, v.x, acc.x);
        acc.y = fmaf(wc, v.y, acc.y);
        acc.z = fmaf(wc, v.z, acc.z);
        acc.w = fmaf(wc, v.w, acc.w);
        c = cn;
    }
    acc.x *= di; acc.y *= di; acc.z *= di; acc.w *= di;
    dst[(size_t)w * 32 + lane] = acc;
}

// ---------------- bf16 split-precision tensor-core GEMM ------------------------
// out[m, n0+j] = (relu?)( sum_k A[m,k] * W[k, n0+j] + bias[n0+j] ),  K = 128 fixed.
// A fp32 row-major (ld = 128). Wt hi/lo bf16 layout [N][K]. 128x128 output tile.
__device__ __forceinline__ void mma16816(float* c, const unsigned* a, unsigned b0, unsigned b1) {
    asm volatile(
        "mma.sync.aligned.m16n8k16.row.col.f32.bf16.bf16.f32 "
        "{%0,%1,%2,%3},{%4,%5,%6,%7},{%8,%9},{%0,%1,%2,%3};"
        : "+f"(c[0]), "+f"(c[1]), "+f"(c[2]), "+f"(c[3])
        : "r"(a[0]), "r"(a[1]), "r"(a[2]), "r"(a[3]), "r"(b0), "r"(b1));
}

#define KSTR 136   // smem row stride in bf16 elements

template<bool RELU>
__global__ void k_gemm_tc(const float* __restrict__ A, const __nv_bfloat16* __restrict__ WtH,
                          const __nv_bfloat16* __restrict__ WtL, const float* __restrict__ bias,
                          float* __restrict__ out, int nrows, int ldc) {
    extern __shared__ __nv_bfloat16 smb[];
    __nv_bfloat16* AsH = smb;
    __nv_bfloat16* AsL = AsH + 128 * KSTR;
    __nv_bfloat16* WsH = AsL + 128 * KSTR;
    __nv_bfloat16* WsL = WsH + 128 * KSTR;

    int tid = threadIdx.x;
    int m0 = blockIdx.x * 128;
    int n0 = blockIdx.y * 128;

    // stage A: fp32 -> bf16 hi/lo
#pragma unroll
    for (int it = 0; it < 16; it++) {
        int i = tid + 256 * it;          // 0..4095
        int r = i >> 5, c4 = i & 31;
        float4 v = (m0 + r < nrows) ? ((const float4*)A)[(size_t)(m0 + r) * 32 + c4]
                                    : make_float4(0.f, 0.f, 0.f, 0.f);
        __nv_bfloat16 h0 = __float2bfloat16(v.x), h1 = __float2bfloat16(v.y);
        __nv_bfloat16 h2 = __float2bfloat16(v.z), h3 = __float2bfloat16(v.w);
        __nv_bfloat16 l0 = __float2bfloat16(v.x - __bfloat162float(h0));
        __nv_bfloat16 l1 = __float2bfloat16(v.y - __bfloat162float(h1));
        __nv_bfloat16 l2 = __float2bfloat16(v.z - __bfloat162float(h2));
        __nv_bfloat16 l3 = __float2bfloat16(v.w - __bfloat162float(h3));
        int o = r * KSTR + c4 * 4;
        *(__nv_bfloat162*)&AsH[o]     = __nv_bfloat162{h0, h1};
        *(__nv_bfloat162*)&AsH[o + 2] = __nv_bfloat162{h2, h3};
        *(__nv_bfloat162*)&AsL[o]     = __nv_bfloat162{l0, l1};
        *(__nv_bfloat162*)&AsL[o + 2] = __nv_bfloat162{l2, l3};
    }
    // stage Wt slice (rows n0..n0+127), straight copy, 16B chunks
    {
        const uint4* GH = (const uint4*)(WtH + (size_t)n0 * 128);
        const uint4* GL = (const uint4*)(WtL + (size_t)n0 * 128);
#pragma unroll
        for (int it = 0; it < 8; it++) {
            int i = tid + 256 * it;      // 0..2047
            int r = i >> 4, c = i & 15;
            *(uint4*)((char*)WsH + r * (KSTR * 2) + c * 16) = GH[r * 16 + c];
            *(uint4*)((char*)WsL + r * (KSTR * 2) + c * 16) = GL[r * 16 + c];
        }
    }
    __syncthreads();

    int lane = tid & 31, wid = tid >> 5;
    int wm = (wid & 3) * 32;
    int wn = (wid >> 2) * 64;
    int g = lane >> 2, t = lane & 3;

    float acc[2][8][4];
#pragma unroll
    for (int mt = 0; mt < 2; mt++)
#pragma unroll
        for (int nt = 0; nt < 8; nt++)
#pragma unroll
            for (int q = 0; q < 4; q++) acc[mt][nt][q] = 0.f;

#pragma unroll
    for (int ks = 0; ks < 8; ks++) {
        int k0 = ks * 16;
        unsigned aH[2][4], aL[2][4];
#pragma unroll
        for (int mt = 0; mt < 2; mt++) {
            int r = wm + mt * 16;
            aH[mt][0] = *(const unsigned*)&AsH[(r + g) * KSTR + k0 + 2 * t];
            aH[mt][1] = *(const unsigned*)&AsH[(r + g + 8) * KSTR + k0 + 2 * t];
            aH[mt][2] = *(const unsigned*)&AsH[(r + g) * KSTR + k0 + 8 + 2 * t];
            aH[mt][3] = *(const unsigned*)&AsH[(r + g + 8) * KSTR + k0 + 8 + 2 * t];
            aL[mt][0] = *(const unsigned*)&AsL[(r + g) * KSTR + k0 + 2 * t];
            aL[mt][1] = *(const unsigned*)&AsL[(r + g + 8) * KSTR + k0 + 2 * t];
            aL[mt][2] = *(const unsigned*)&AsL[(r + g) * KSTR + k0 + 8 + 2 * t];
            aL[mt][3] = *(const unsigned*)&AsL[(r + g + 8) * KSTR + k0 + 8 + 2 * t];
        }
#pragma unroll
        for (int nt = 0; nt < 8; nt++) {
            int nn = wn + nt * 8 + g;
            unsigned bH0 = *(const unsigned*)&WsH[nn * KSTR + k0 + 2 * t];
            unsigned bH1 = *(const unsigned*)&WsH[nn * KSTR + k0 + 8 + 2 * t];
            unsigned bL0 = *(const unsigned*)&WsL[nn * KSTR + k0 + 2 * t];
            unsigned bL1 = *(const unsigned*)&WsL[nn * KSTR + k0 + 8 + 2 * t];
#pragma unroll
            for (int mt = 0; mt < 2; mt++) {
                mma16816(acc[mt][nt], aH[mt], bH0, bH1);
                mma16816(acc[mt][nt], aH[mt], bL0, bL1);
                mma16816(acc[mt][nt], aL[mt], bH0, bH1);
            }
        }
    }

    // epilogue
#pragma unroll
    for (int nt = 0; nt < 8; nt++) {
        int cg = n0 + wn + nt * 8 + 2 * t;
        float bv0 = bias[cg], bv1 = bias[cg + 1];
#pragma unroll
        for (int mt = 0; mt < 2; mt++) {
            int r0 = m0 + wm + mt * 16 + g;
            float v0 = acc[mt][nt][0] + bv0, v1 = acc[mt][nt][1] + bv1;
            float v2 = acc[mt][nt][2] + bv0, v3 = acc[mt][nt][3] + bv1;
            if (RELU) {
                v0 = fmaxf(v0, 0.f); v1 = fmaxf(v1, 0.f);
                v2 = fmaxf(v2, 0.f); v3 = fmaxf(v3, 0.f);
            }
            if (r0 < nrows) {
                out[(size_t)r0 * ldc + cg]     = v0;
                out[(size_t)r0 * ldc + cg + 1] = v1;
            }
            if (r0 + 8 < nrows) {
                out[(size_t)(r0 + 8) * ldc + cg]     = v2;
                out[(size_t)(r0 + 8) * ldc + cg + 1] = v3;
            }
        }
    }
}

#define SMEM_TC (4 * 128 * KSTR * 2)   // 139264 bytes

// ---------------- fp32 GEMM (kept for MLP2: K=256, N=40) -----------------------
template<int K, int NO, int TM, int TN, bool RELU>
__global__ void k_gemm(const float* __restrict__ A, const float* __restrict__ W,
                       const float* __restrict__ bias, float* __restrict__ out, int n) {
    constexpr int TX     = NO / TN;
    constexpr int TY     = 256 / TX;
    constexpr int TILE_M = TY * TM;
    constexpr int KP     = K + 1;
    extern __shared__ float smf[];
    float* Ws = smf;
    float* As = smf + K * NO;

    int tid = threadIdx.x;
    {
        const float4* W4  = (const float4*)W;
        float4*       Ws4 = (float4*)Ws;
        for (int i = tid; i < K * NO / 4; i += 256) Ws4[i] = W4[i];
    }
    int m0 = blockIdx.x * TILE_M;
    for (int i = tid; i < TILE_M * K / 4; i += 256) {
        int r = (i * 4) / K, k = (i * 4) % K;
        int gr = m0 + r;
        float4 v = (gr < n) ? ((const float4*)A)[(size_t)gr * (K / 4) + (k / 4)]
                            : make_float4(0.f, 0.f, 0.f, 0.f);
        As[r * KP + k]     = v.x;
        As[r * KP + k + 1] = v.y;
        As[r * KP + k + 2] = v.z;
        As[r * KP + k + 3] = v.w;
    }
    __syncthreads();

    int tx = tid % TX, ty = tid / TX;
    float acc[TM][TN];
#pragma unroll
    for (int i = 0; i < TM; i++)
#pragma unroll
        for (int j = 0; j < TN; j++) acc[i][j] = 0.f;

#pragma unroll 8
    for (int k = 0; k < K; k++) {
        float a[TM];
#pragma unroll
        for (int i = 0; i < TM; i++) a[i] = As[(ty * TM + i) * KP + k];
        float w[TN];
#pragma unroll
        for (int j = 0; j < TN; j++) w[j] = Ws[k * NO + tx * TN + j];
#pragma unroll
        for (int i = 0; i < TM; i++)
#pragma unroll
            for (int j = 0; j < TN; j++)
                acc[i][j] = fmaf(a[i], w[j], acc[i][j]);
    }

    float bv[TN];
#pragma unroll
    for (int j = 0; j < TN; j++) bv[j] = bias[tx * TN + j];

#pragma unroll
    for (int i = 0; i < TM; i++) {
        int gr = m0 + ty * TM + i;
        if (gr < n) {
#pragma unroll
            for (int j = 0; j < TN; j++) {
                float v = acc[i][j] + bv[j];
                if (RELU) v = fmaxf(v, 0.f);
                out[(size_t)gr * NO + tx * TN + j] = v;
            }
        }
    }
}

#define SMEM_MLP2 ((256 * 40 + 64 * 257) * 4)

extern "C" void kernel_launch(void* const* d_in, const int* in_sizes, int n_in,
                              void* d_out, int out_size) {
    const float* x   = (const float*)d_in[0];
    const int*   ei  = (const int*)  d_in[1];
    const float* W0  = (const float*)d_in[2];
    const float* b0  = (const float*)d_in[3];
    const float* W1  = (const float*)d_in[4];
    const float* b1  = (const float*)d_in[5];
    const float* W2  = (const float*)d_in[6];
    const float* b2  = (const float*)d_in[7];
    const float* Wm1 = (const float*)d_in[8];
    const float* bm1 = (const float*)d_in[9];
    const float* Wm2 = (const float*)d_in[10];
    const float* bm2 = (const float*)d_in[11];
    float* out = (float*)d_out;

    const int n = Nn, e = Ee;

    int *degi, *offs, *col, *part, *base;
    float *dinv, *bufA, *bufB, *hid;
    __nv_bfloat16 *wtH, *wtL;
    cudaGetSymbolAddress((void**)&degi, g_degi);
    cudaGetSymbolAddress((void**)&offs, g_offs);
    cudaGetSymbolAddress((void**)&col,  g_col);
    cudaGetSymbolAddress((void**)&part, g_part);
    cudaGetSymbolAddress((void**)&base, g_base);
    cudaGetSymbolAddress((void**)&dinv, g_dinv);
    cudaGetSymbolAddress((void**)&bufA, g_bufA);
    cudaGetSymbolAddress((void**)&bufB, g_bufB);
    cudaGetSymbolAddress((void**)&hid,  g_hid);
    cudaGetSymbolAddress((void**)&wtH,  g_wtH);
    cudaGetSymbolAddress((void**)&wtL,  g_wtL);

    cudaFuncSetAttribute(k_gemm_tc<true>,
                         cudaFuncAttributeMaxDynamicSharedMemorySize, SMEM_TC);
    cudaFuncSetAttribute(k_gemm_tc<false>,
                         cudaFuncAttributeMaxDynamicSharedMemorySize, SMEM_TC);
    cudaFuncSetAttribute(k_gemm<256, 40, 1, 10, false>,
                         cudaFuncAttributeMaxDynamicSharedMemorySize, SMEM_MLP2);

    const int TB = 256;
    dim3 gN((n + TB - 1) / TB);
    dim3 gE((e + TB - 1) / TB);
    dim3 gNW(((size_t)n * 32 + TB - 1) / TB);
    dim3 gTC((n + 127) / 128, 1);
    dim3 gTC2((n + 127) / 128, 2);
    dim3 gGemm64((n + 63) / 64);

    // ---- CSR build + normalization ----
    k_zero <<<gN, TB>>>(degi, n);
    k_count<<<gE, TB>>>(ei, degi, e);
    k_dinv <<<gN, TB>>>(degi, dinv, n);
    k_scanA<<<NB, 1024>>>(degi, part);
    k_scanB<<<1, 128>>>(part, base);
    k_scanC<<<NB, 1024>>>(degi, base, offs);
    k_fill <<<gE, TB>>>(ei, offs, degi, col, e);

    // ---- weight conversion (transposed bf16 hi/lo) ----
    k_wconv<<<(128 * 128 + 255) / 256, 256>>>(W0,  wtH + WT0,  wtL + WT0,  128, 128);
    k_wconv<<<(128 * 128 + 255) / 256, 256>>>(W1,  wtH + WT1,  wtL + WT1,  128, 128);
    k_wconv<<<(128 * 128 + 255) / 256, 256>>>(W2,  wtH + WT2,  wtL + WT2,  128, 128);
    k_wconv<<<(128 * 256 + 255) / 256, 256>>>(Wm1, wtH + WTM1, wtL + WTM1, 128, 256);

    // ---- layer 0 ----
    k_gather<<<gNW, TB>>>(offs, col, dinv, (const float4*)x, (float4*)bufA);
    k_gemm_tc<true><<<gTC, TB, SMEM_TC>>>(bufA, wtH + WT0, wtL + WT0, b0, bufB, n, 128);
    // ---- layer 1 ----
    k_gather<<<gNW, TB>>>(offs, col, dinv, (const float4*)bufB, (float4*)bufA);
    k_gemm_tc<true><<<gTC, TB, SMEM_TC>>>(bufA, wtH + WT1, wtL + WT1, b1, bufB, n, 128);
    // ---- layer 2 ----
    k_gather<<<gNW, TB>>>(offs, col, dinv, (const float4*)bufB, (float4*)bufA);
    k_gemm_tc<true><<<gTC, TB, SMEM_TC>>>(bufA, wtH + WT2, wtL + WT2, b2, bufB, n, 128);

    // ---- MLP ----
    k_gemm_tc<true><<<gTC2, TB, SMEM_TC>>>(bufB, wtH + WTM1, wtL + WTM1, bm1, hid, n, 256);
    k_gemm<256, 40, 1, 10, false><<<gGemm64, TB, SMEM_MLP2>>>(hid, Wm2, bm2, out, n);
}